// round 11
// baseline (speedup 1.0000x reference)
#include <cuda_runtime.h>

// FIR: out[b,t,c] = sum_{i=0..15} w[i,c] * x[b, t-15+i, c]   (causal, zero-padded)
// x: [B=64, T=2048, C=32] fp32, w: [F=16, C=32] fp32, out: [B, T, C] fp32.
//
// Round 11 == Round 10 resubmitted unchanged: R10 failed with a harness-side
// "device busy or unavailable" at context init (infra), so the GRP=16
// streaming-accumulator theory is untested. Thread = channel pair x 16
// timesteps: 16 packed accs + 16 packed taps, stream 31 window values (each
// consumed immediately). Loads per 32 outputs 78 -> 47 vs R9; 1024 blocks
// ~= 1.1 waves at 6 blocks/SM.

#define B_SZ 64
#define T_SZ 2048
#define C_SZ 32
#define F_SZ 16
#define GRP  16
#define HALO (F_SZ - 1)          // 15
#define WIN  (GRP + HALO)        // 31
#define NPAIR (C_SZ / 2)         // 16
#define THREADS 128

typedef unsigned long long u64;

__device__ __forceinline__ u64 fma2(u64 a, u64 b, u64 c) {
    u64 d;
    asm("fma.rn.f32x2 %0, %1, %2, %3;" : "=l"(d) : "l"(a), "l"(b), "l"(c));
    return d;
}

__global__ __launch_bounds__(THREADS, 6)   // cap <= 85 regs/thread
void fir_kernel(const float* __restrict__ x,
                const float* __restrict__ w,
                float* __restrict__ out) {
    // item id -> (b, time-group, channel-pair); lanes 0..15 share tg and step
    // cp, so each half-warp LDG.64 covers one full 128B line.
    const int g  = blockIdx.x * THREADS + threadIdx.x;
    const int cp = g & (NPAIR - 1);
    const int tg = (g >> 4) & (T_SZ / GRP - 1);   // 0..127
    const int b  = g >> 11;
    const int t0 = tg * GRP;

    const long base = ((long)b * T_SZ + t0) * NPAIR + cp;
    const u64* xp = (const u64*)x + base;

    // taps for this channel pair (L1-hot after first warp per SM)
    u64 wp[F_SZ];
    const u64* wpr = (const u64*)w;               // [16][16] pairs
#pragma unroll
    for (int i = 0; i < F_SZ; i++) wp[i] = wpr[i * NPAIR + cp];

    u64 acc[GRP];
#pragma unroll
    for (int u = 0; u < GRP; u++) acc[u] = 0ULL;

    if (tg != 0) {
        // full window in-bounds: stream 31 values, fma into live accs
#pragma unroll
        for (int j = 0; j < WIN; j++) {
            const u64 xv = xp[(j - HALO) * NPAIR];
            const int ulo = (j - HALO < 0) ? 0 : j - HALO;
            const int uhi = (j < GRP - 1) ? j : GRP - 1;
#pragma unroll
            for (int u = ulo; u <= uhi; u++)
                acc[u] = fma2(wp[j - u], xv, acc[u]);
        }
    } else {
        // t0 == 0: window entries j < 15 are zero-padding -> skip entirely
#pragma unroll
        for (int j = HALO; j < WIN; j++) {
            const u64 xv = xp[(j - HALO) * NPAIR];
            const int ulo = j - HALO;
            const int uhi = (j < GRP - 1) ? j : GRP - 1;
#pragma unroll
            for (int u = ulo; u <= uhi; u++)
                acc[u] = fma2(wp[j - u], xv, acc[u]);
        }
    }

    u64* op = (u64*)out + base;
#pragma unroll
    for (int u = 0; u < GRP; u++)
        op[u * NPAIR] = acc[u];
}

extern "C" void kernel_launch(void* const* d_in, const int* in_sizes, int n_in,
                              void* d_out, int out_size) {
    const float* x = (const float*)d_in[0];   // [64, 2048, 32]
    const float* w = (const float*)d_in[1];   // [16, 32]
    float* out = (float*)d_out;

    const int total = B_SZ * (T_SZ / GRP) * NPAIR;       // 131072 threads
    fir_kernel<<<total / THREADS, THREADS>>>(x, w, out); // 1024 blocks
}

// round 13
// speedup vs baseline: 1.1845x; 1.1845x over previous
#include <cuda_runtime.h>

// FIR: out[b,t,c] = sum_{i=0..15} w[i,c] * x[b, t-15+i, c]   (causal, zero-padded)
// x: [B=64, T=2048, C=32] fp32, w: [F=16, C=32] fp32, out: [B, T, C] fp32.
//
// Round 13: R12 (two items/thread, streaming accs, GRP=8, 64-reg cap) with the
// edge handling fixed: with GRP=8 BOTH tg==0 (skip 15 window entries) and
// tg==1 (skip 7) need zero-padding; R12 only handled tg==0 and read the
// previous batch's tail for tg==1 (rel_err 2.8e-2, same as the R7 bug).

#define B_SZ 64
#define T_SZ 2048
#define C_SZ 32
#define F_SZ 16
#define GRP  8
#define HALO (F_SZ - 1)          // 15
#define WIN  (GRP + HALO)        // 23
#define NPAIR (C_SZ / 2)         // 16
#define THREADS 128
#define TG_HALF 128              // item2 = item1 + 128 time-groups

typedef unsigned long long u64;

__device__ __forceinline__ u64 fma2(u64 a, u64 b, u64 c) {
    u64 d;
    asm("fma.rn.f32x2 %0, %1, %2, %3;" : "=l"(d) : "l"(a), "l"(b), "l"(c));
    return d;
}
__device__ __forceinline__ u64 mul2(u64 a, u64 b) {
    u64 d;
    asm("mul.rn.f32x2 %0, %1, %2;" : "=l"(d) : "l"(a), "l"(b));
    return d;
}

// One 8-timestep item for one channel pair. J0 = number of leading window
// entries that are zero padding (skipped entirely): 15 for t0=0, 7 for t0=8,
// 0 otherwise. acc[u] is first touched at j == max(u, J0) -> mul2 init.
template <int J0>
__device__ __forceinline__ void fir_item(const u64* __restrict__ xp,
                                         u64* __restrict__ op,
                                         const u64 wp[F_SZ]) {
    u64 acc[GRP];
#pragma unroll
    for (int j = J0; j < WIN; j++) {
        const u64 xv = xp[(j - HALO) * NPAIR];
        const int ulo = (j - HALO < 0) ? 0 : j - HALO;
        const int uhi = (j < GRP - 1) ? j : GRP - 1;
#pragma unroll
        for (int u = ulo; u <= uhi; u++) {
            const bool first = (j == (u > J0 ? u : J0));
            acc[u] = first ? mul2(wp[j - u], xv)
                           : fma2(wp[j - u], xv, acc[u]);
        }
    }
#pragma unroll
    for (int u = 0; u < GRP; u++)
        op[u * NPAIR] = acc[u];
}

__global__ __launch_bounds__(THREADS, 8)   // cap 64 regs/thread
void fir_kernel(const float* __restrict__ x,
                const float* __restrict__ w,
                float* __restrict__ out) {
    // thread -> (b, tg in 0..127, cp); item2 = tg + 128. Lanes 0..15 share tg
    // and step cp, so each half-warp LDG.64 covers one 128B line.
    const int g  = blockIdx.x * THREADS + threadIdx.x;
    const int cp = g & (NPAIR - 1);
    const int tg = (g >> 4) & (TG_HALF - 1);      // 0..127
    const int b  = g >> 11;                       // 0..63

    const long base1 = ((long)b * T_SZ + tg * GRP) * NPAIR + cp;
    const long base2 = base1 + (long)TG_HALF * GRP * NPAIR;

    // taps for this channel pair, loaded once for both items (L1-hot)
    u64 wp[F_SZ];
    const u64* wpr = (const u64*)w;               // [16][16] pairs
#pragma unroll
    for (int i = 0; i < F_SZ; i++) wp[i] = wpr[i * NPAIR + cp];

    if (tg == 0)
        fir_item<HALO>((const u64*)x + base1, (u64*)out + base1, wp);      // t0 = 0
    else if (tg == 1)
        fir_item<HALO - GRP>((const u64*)x + base1, (u64*)out + base1, wp); // t0 = 8
    else
        fir_item<0>((const u64*)x + base1, (u64*)out + base1, wp);

    fir_item<0>((const u64*)x + base2, (u64*)out + base2, wp);  // tg+128 >= 2 always

    // note: J0 = HALO-GRP = 7 entries skipped for t0=8 (times -7..-1 are padding)
}

extern "C" void kernel_launch(void* const* d_in, const int* in_sizes, int n_in,
                              void* d_out, int out_size) {
    const float* x = (const float*)d_in[0];   // [64, 2048, 32]
    const float* w = (const float*)d_in[1];   // [16, 32]
    float* out = (float*)d_out;

    const int total = B_SZ * TG_HALF * NPAIR;            // 131072 threads
    fir_kernel<<<total / THREADS, THREADS>>>(x, w, out); // 1024 blocks
}